// round 1
// baseline (speedup 1.0000x reference)
#include <cuda_runtime.h>

// SSIM_79886391705722 — fused separable-Gaussian SSIM on GB300.
// raw/dst: [32,3,512,512] f32. Crop 4px border -> 504x504, *255,
// 11x11 gaussian depthwise conv (valid) -> 494x494, SSIM map, mean per batch.

#define TILE      32
#define IN_T      42            // TILE + 10 halo
#define PITCH_IN  45            // conflict-free for stride-4 strip reads
#define PITCH_H   33            // conflict-free h-plane stores/reads
#define OUT_DIM   494
#define CROP_LAST 507           // last valid raw row/col index (4..507)

__global__ __launch_bounds__(32) void ssim_zero(float* out) {
    out[threadIdx.x] = 0.0f;
}

__global__ __launch_bounds__(32) void ssim_scale(float* out) {
    out[threadIdx.x] *= (1.0f / (3.0f * 494.0f * 494.0f));
}

__global__ __launch_bounds__(256) void ssim_main(const float* __restrict__ raw,
                                                 const float* __restrict__ dst,
                                                 float* __restrict__ out) {
    __shared__ float s_r[IN_T * PITCH_IN];
    __shared__ float s_d[IN_T * PITCH_IN];
    __shared__ float s_h[5][IN_T * PITCH_H];
    __shared__ float s_red[8];

    const int tid = threadIdx.x;
    const int z   = blockIdx.z;                 // b*3 + c
    const size_t plane = (size_t)z * 512 * 512;
    const float* rp = raw + plane;
    const float* dp = dst + plane;

    // Gaussian weights (normalized 1D), fp32 like the reference.
    float g[11];
    {
        float s = 0.0f;
        #pragma unroll
        for (int i = 0; i < 11; i++) {
            float t = (float)(i - 5);
            g[i] = expf(-(t * t) / (2.0f * 1.5f * 1.5f));
            s += g[i];
        }
        float inv = 1.0f / s;
        #pragma unroll
        for (int i = 0; i < 11; i++) g[i] *= inv;
    }

    // ---- Phase 1: load halo tile (42x42) of r and d, scaled by 255 ----
    const int row0 = blockIdx.y * TILE + 4;
    const int col0 = blockIdx.x * TILE + 4;
    for (int i = tid; i < IN_T * IN_T; i += 256) {
        int y = i / IN_T, x = i - y * IN_T;
        int gr = row0 + y, gc = col0 + x;
        float rv = 0.0f, dv = 0.0f;
        if (gr <= CROP_LAST && gc <= CROP_LAST) {
            size_t off = (size_t)gr * 512 + gc;
            rv = __ldg(rp + off) * 255.0f;
            dv = __ldg(dp + off) * 255.0f;
        }
        s_r[y * PITCH_IN + x] = rv;
        s_d[y * PITCH_IN + x] = dv;
    }
    __syncthreads();

    // ---- Phase 2: horizontal 11-tap pass on 5 channels ----
    // Tasks: 42 rows x 8 strips of 4 outputs each = 336 tasks.
    for (int task = tid; task < IN_T * 8; task += 256) {
        int y  = task >> 3;
        int x0 = (task & 7) << 2;
        float ar[4]  = {0, 0, 0, 0};
        float ad[4]  = {0, 0, 0, 0};
        float arr[4] = {0, 0, 0, 0};
        float add2[4] = {0, 0, 0, 0};
        float ard[4] = {0, 0, 0, 0};
        #pragma unroll
        for (int i = 0; i < 14; i++) {
            float rv = s_r[y * PITCH_IN + x0 + i];
            float dv = s_d[y * PITCH_IN + x0 + i];
            float rr = rv * rv, dd = dv * dv, rd = rv * dv;
            #pragma unroll
            for (int k = 0; k < 4; k++) {
                int j = i - k;
                if (j >= 0 && j < 11) {
                    float w = g[j];
                    ar[k]  += w * rv;
                    ad[k]  += w * dv;
                    arr[k] += w * rr;
                    add2[k] += w * dd;
                    ard[k] += w * rd;
                }
            }
        }
        #pragma unroll
        for (int k = 0; k < 4; k++) {
            int idx = y * PITCH_H + x0 + k;
            s_h[0][idx] = ar[k];
            s_h[1][idx] = ad[k];
            s_h[2][idx] = arr[k];
            s_h[3][idx] = add2[k];
            s_h[4][idx] = ard[k];
        }
    }
    __syncthreads();

    // ---- Phase 3: vertical 11-tap pass + SSIM + reduce ----
    // Exactly 256 tasks: x = tid%32, y-strip of 4 = tid/32.
    float local = 0.0f;
    {
        int x  = tid & 31;
        int y0 = (tid >> 5) << 2;
        float mr[4]  = {0, 0, 0, 0};
        float md[4]  = {0, 0, 0, 0};
        float srr[4] = {0, 0, 0, 0};
        float sdd[4] = {0, 0, 0, 0};
        float srd[4] = {0, 0, 0, 0};
        #pragma unroll
        for (int j = 0; j < 14; j++) {
            int idx = (y0 + j) * PITCH_H + x;
            float hr  = s_h[0][idx];
            float hd  = s_h[1][idx];
            float hrr = s_h[2][idx];
            float hdd = s_h[3][idx];
            float hrd = s_h[4][idx];
            #pragma unroll
            for (int k = 0; k < 4; k++) {
                int t = j - k;
                if (t >= 0 && t < 11) {
                    float w = g[t];
                    mr[k]  += w * hr;
                    md[k]  += w * hd;
                    srr[k] += w * hrr;
                    sdd[k] += w * hdd;
                    srd[k] += w * hrd;
                }
            }
        }
        const float C1 = 6.5025f;    // (0.01*255)^2
        const float C2 = 58.5225f;   // (0.03*255)^2
        int ox = blockIdx.x * TILE + x;
        int oyb = blockIdx.y * TILE + y0;
        #pragma unroll
        for (int k = 0; k < 4; k++) {
            if (ox < OUT_DIM && (oyb + k) < OUT_DIM) {
                float a = mr[k], b = md[k];
                float ab  = a * b;
                float cov = srd[k] - ab;
                float var = (srr[k] - a * a) + (sdd[k] - b * b);
                float num = (2.0f * ab + C1) * (2.0f * cov + C2);
                float den = (a * a + b * b + C1) * (var + C2);
                local += num / den;
            }
        }
    }

    // Block reduction
    #pragma unroll
    for (int o = 16; o > 0; o >>= 1)
        local += __shfl_down_sync(0xffffffff, local, o);
    if ((tid & 31) == 0) s_red[tid >> 5] = local;
    __syncthreads();
    if (tid < 8) {
        local = s_red[tid];
        #pragma unroll
        for (int o = 4; o > 0; o >>= 1)
            local += __shfl_down_sync(0xff, local, o);
        if (tid == 0) atomicAdd(&out[z / 3], local);
    }
}

extern "C" void kernel_launch(void* const* d_in, const int* in_sizes, int n_in,
                              void* d_out, int out_size) {
    const float* raw = (const float*)d_in[0];
    const float* dst = (const float*)d_in[1];
    float* out = (float*)d_out;

    ssim_zero<<<1, 32>>>(out);
    dim3 grid(16, 16, 96);   // 16x16 tiles of 32x32 over 494x494, z = b*3+c
    ssim_main<<<grid, 256>>>(raw, dst, out);
    ssim_scale<<<1, 32>>>(out);
}

// round 2
// speedup vs baseline: 1.4499x; 1.4499x over previous
#include <cuda_runtime.h>

// SSIM_79886391705722 — fused separable-Gaussian SSIM, f32x2-packed, GB300.
// raw/dst: [32,3,512,512] f32. Crop 4 -> 504x504, *255, 11x11 gaussian
// depthwise (valid) -> 494x494, SSIM map, per-batch mean [32].

typedef unsigned long long u64;

#define TILE      32
#define IN_T      42           // TILE + 10 halo
#define PITCH_RD  45           // u64 units (odd), with x+(x>>4) gap swizzle
#define PITCH_H   34           // u64 planes, with gap swizzle
#define PITCH_S   33           // scalar rd plane, no swizzle
#define OUT_DIM   494
#define CROP_LAST 507

// Normalized 1D Gaussian (ws=11, sigma=1.5), matches reference to ~1e-7.
#define G0  0.00102838f
#define G1  0.00759875f
#define G2  0.03600078f
#define G3  0.10936070f
#define G4  0.21300554f
#define G5  0.26601173f

__device__ __forceinline__ u64 pack2(float lo, float hi) {
    u64 r; asm("mov.b64 %0, {%1,%2};" : "=l"(r) : "f"(lo), "f"(hi)); return r;
}
__device__ __forceinline__ void unpack2(u64 v, float& lo, float& hi) {
    asm("mov.b64 {%0,%1}, %2;" : "=f"(lo), "=f"(hi) : "l"(v));
}
__device__ __forceinline__ u64 mul2(u64 a, u64 b) {
    u64 r; asm("mul.rn.f32x2 %0, %1, %2;" : "=l"(r) : "l"(a), "l"(b)); return r;
}
__device__ __forceinline__ u64 fma2(u64 a, u64 b, u64 c) {
    u64 r; asm("fma.rn.f32x2 %0, %1, %2, %3;" : "=l"(r) : "l"(a), "l"(b), "l"(c)); return r;
}

__global__ __launch_bounds__(32) void ssim_zero(float* out) {
    out[threadIdx.x] = 0.0f;
}

__global__ __launch_bounds__(256) void ssim_main(const float* __restrict__ raw,
                                                 const float* __restrict__ dst,
                                                 float* __restrict__ out) {
    __shared__ u64   s_rd[IN_T * PITCH_RD];      // (r,d) packed, swizzled x
    __shared__ u64   s_hm[IN_T * PITCH_H];       // (mean_r, mean_d) h-pass
    __shared__ u64   s_hs[IN_T * PITCH_H];       // (rr, dd) h-pass
    __shared__ float s_hrd[IN_T * PITCH_S];      // rd h-pass
    __shared__ float s_red[8];

    const int tid = threadIdx.x;
    const int z   = blockIdx.z;                  // b*3 + c
    const size_t plane = (size_t)z * 512 * 512;
    const float* rp = raw + plane;
    const float* dp = dst + plane;

    const float g[11]  = {G0, G1, G2, G3, G4, G5, G4, G3, G2, G1, G0};
    u64 g2[11];
    #pragma unroll
    for (int i = 0; i < 11; i++) g2[i] = pack2(g[i], g[i]);

    // ---- Phase 1: load 42x42 halo of (r,d), scaled 255, packed u64 ----
    const int row0 = blockIdx.y * TILE + 4;
    const int col0 = blockIdx.x * TILE + 4;      // always even -> float2 aligned
    for (int i = tid; i < IN_T * 21; i += 256) {
        int y  = i / 21;
        int xp = i - y * 21;
        int x  = xp * 2;
        int gr = row0 + y, gc = col0 + x;
        float r0 = 0.f, r1 = 0.f, d0 = 0.f, d1 = 0.f;
        if (gr <= CROP_LAST) {
            size_t off = (size_t)gr * 512 + gc;   // in-bounds of plane always
            float2 rv = *reinterpret_cast<const float2*>(rp + off);
            float2 dv = *reinterpret_cast<const float2*>(dp + off);
            if (gc     <= CROP_LAST) { r0 = rv.x * 255.0f; d0 = dv.x * 255.0f; }
            if (gc + 1 <= CROP_LAST) { r1 = rv.y * 255.0f; d1 = dv.y * 255.0f; }
        }
        int x0s = x + (x >> 4);
        int x1s = (x + 1) + ((x + 1) >> 4);
        s_rd[y * PITCH_RD + x0s] = pack2(r0, d0);
        s_rd[y * PITCH_RD + x1s] = pack2(r1, d1);
    }
    __syncthreads();

    // ---- Phase 2: horizontal 11-tap on 3 packed chains; 42 rows x 8 strips ----
    for (int task = tid; task < IN_T * 8; task += 256) {
        int y  = task >> 3;
        int x0 = (task & 7) << 2;
        u64 am[4] = {0, 0, 0, 0};
        u64 as_[4] = {0, 0, 0, 0};
        float ard[4] = {0.f, 0.f, 0.f, 0.f};
        const u64* row = &s_rd[y * PITCH_RD];
        #pragma unroll
        for (int i = 0; i < 14; i++) {
            int xs = x0 + i;
            u64 v  = row[xs + (xs >> 4)];
            u64 sq = mul2(v, v);
            float r, d; unpack2(v, r, d);
            float rd = r * d;
            #pragma unroll
            for (int k = 0; k < 4; k++) {
                int j = i - k;
                if (j >= 0 && j < 11) {
                    am[k]  = fma2(g2[j], v, am[k]);
                    as_[k] = fma2(g2[j], sq, as_[k]);
                    ard[k] = fmaf(g[j], rd, ard[k]);
                }
            }
        }
        #pragma unroll
        for (int k = 0; k < 4; k++) {
            int x   = x0 + k;
            int idx = y * PITCH_H + x + (x >> 4);
            s_hm[idx] = am[k];
            s_hs[idx] = as_[k];
            s_hrd[y * PITCH_S + x] = ard[k];
        }
    }
    __syncthreads();

    // ---- Phase 3: vertical 11-tap + SSIM + reduce. 256 tasks exactly ----
    float local = 0.0f;
    {
        int x  = tid & 31;
        int y0 = (tid >> 5) << 2;
        int xi = x + (x >> 4);
        u64 am[4] = {0, 0, 0, 0};
        u64 as_[4] = {0, 0, 0, 0};
        float ard[4] = {0.f, 0.f, 0.f, 0.f};
        #pragma unroll
        for (int j = 0; j < 14; j++) {
            int idx = (y0 + j) * PITCH_H + xi;
            u64 hm = s_hm[idx];
            u64 hs = s_hs[idx];
            float hrd = s_hrd[(y0 + j) * PITCH_S + x];
            #pragma unroll
            for (int k = 0; k < 4; k++) {
                int t = j - k;
                if (t >= 0 && t < 11) {
                    am[k]  = fma2(g2[t], hm, am[k]);
                    as_[k] = fma2(g2[t], hs, as_[k]);
                    ard[k] = fmaf(g[t], hrd, ard[k]);
                }
            }
        }
        const float C1 = 6.5025f;
        const float C2 = 58.5225f;
        int ox  = blockIdx.x * TILE + x;
        int oyb = blockIdx.y * TILE + y0;
        #pragma unroll
        for (int k = 0; k < 4; k++) {
            if (ox < OUT_DIM && (oyb + k) < OUT_DIM) {
                float a, b, srr, sdd;
                unpack2(am[k], a, b);
                unpack2(as_[k], srr, sdd);
                float ab  = a * b;
                float cov = ard[k] - ab;
                float var = (srr - a * a) + (sdd - b * b);
                float num = (2.0f * ab + C1) * (2.0f * cov + C2);
                float den = (a * a + b * b + C1) * (var + C2);
                local += __fdividef(num, den);
            }
        }
    }

    #pragma unroll
    for (int o = 16; o > 0; o >>= 1)
        local += __shfl_down_sync(0xffffffff, local, o);
    if ((tid & 31) == 0) s_red[tid >> 5] = local;
    __syncthreads();
    if (tid < 8) {
        local = s_red[tid];
        #pragma unroll
        for (int o = 4; o > 0; o >>= 1)
            local += __shfl_down_sync(0xff, local, o);
        if (tid == 0)
            atomicAdd(&out[z / 3], local * (1.0f / 732108.0f)); // 1/(3*494^2)
    }
}

extern "C" void kernel_launch(void* const* d_in, const int* in_sizes, int n_in,
                              void* d_out, int out_size) {
    const float* raw = (const float*)d_in[0];
    const float* dst = (const float*)d_in[1];
    float* out = (float*)d_out;

    ssim_zero<<<1, 32>>>(out);
    dim3 grid(16, 16, 96);
    ssim_main<<<grid, 256>>>(raw, dst, out);
}

// round 3
// speedup vs baseline: 1.9011x; 1.3112x over previous
#include <cuda_runtime.h>

// SSIM_79886391705722 — fused separable-Gaussian SSIM, f32x2, conflict-free
// layout (no swizzle ALU), 4-channel packing. GB300 sm_103a.
// raw/dst: [32,3,512,512] f32. Crop 4 -> *255 -> 11x11 gaussian (valid)
// -> 494x494 SSIM map -> per-batch mean [32].

typedef unsigned long long u64;

#define TILE_W  32
#define TILE_H  40
#define IN_W    42
#define IN_H    50
#define P_RD    43     // u64 pitch, odd -> conflict-free for 16-row half-warps
#define P_H     33     // u64 pitch, odd
#define OUT_DIM 494
#define CROP_LAST 507

// Normalized 1D Gaussian (ws=11, sigma=1.5)
#define G0 0.00102838f
#define G1 0.00759875f
#define G2 0.03600078f
#define G3 0.10936070f
#define G4 0.21300554f
#define G5 0.26601173f

__device__ __forceinline__ u64 pack2(float lo, float hi) {
    u64 r; asm("mov.b64 %0, {%1,%2};" : "=l"(r) : "f"(lo), "f"(hi)); return r;
}
__device__ __forceinline__ void unpack2(u64 v, float& lo, float& hi) {
    asm("mov.b64 {%0,%1}, %2;" : "=f"(lo), "=f"(hi) : "l"(v));
}
__device__ __forceinline__ u64 mul2(u64 a, u64 b) {
    u64 r; asm("mul.rn.f32x2 %0, %1, %2;" : "=l"(r) : "l"(a), "l"(b)); return r;
}
__device__ __forceinline__ u64 fma2(u64 a, u64 b, u64 c) {
    u64 r; asm("fma.rn.f32x2 %0, %1, %2, %3;" : "=l"(r) : "l"(a), "l"(b), "l"(c)); return r;
}

__global__ __launch_bounds__(32) void ssim_zero(float* out) {
    out[threadIdx.x] = 0.0f;
}

__global__ __launch_bounds__(256) void ssim_main(const float* __restrict__ raw,
                                                 const float* __restrict__ dst,
                                                 float* __restrict__ out) {
    __shared__ u64 s_rd[IN_H * P_RD];   // (r, d)            43*50*8   = 17.2KB
    __shared__ u64 s_hm[IN_H * P_H];    // h-pass (mr, md)   33*50*8   = 13.2KB
    __shared__ u64 s_hq[IN_H * P_H];    // h-pass (rr+dd, rd)          = 13.2KB
    __shared__ float s_red[8];

    const int tid = threadIdx.x;
    const int z   = blockIdx.z;                  // b*3 + c
    const size_t plane = (size_t)z * 512 * 512;
    const float* rp = raw + plane;
    const float* dp = dst + plane;

    const float g[11] = {G0, G1, G2, G3, G4, G5, G4, G3, G2, G1, G0};
    u64 g2[11];
    #pragma unroll
    for (int i = 0; i < 11; i++) g2[i] = pack2(g[i], g[i]);

    // ---- Phase 1: load 50x42 halo of (r,d)*255 as packed u64, row-major ----
    const int row0 = blockIdx.y * TILE_H + 4;
    const int col0 = blockIdx.x * TILE_W + 4;    // even -> float2 aligned
    for (int i = tid; i < IN_H * 21; i += 256) {
        int y  = i / 21;
        int xp = i - y * 21;
        int x  = xp * 2;
        int gr = row0 + y, gc = col0 + x;
        float r0 = 0.f, r1 = 0.f, d0 = 0.f, d1 = 0.f;
        if (gr <= CROP_LAST && gc <= CROP_LAST) {
            size_t off = (size_t)gr * 512 + gc;  // gc+1 <= 511 always in-plane
            float2 rv = *reinterpret_cast<const float2*>(rp + off);
            float2 dv = *reinterpret_cast<const float2*>(dp + off);
            r0 = rv.x * 255.0f; d0 = dv.x * 255.0f;
            if (gc + 1 <= CROP_LAST) { r1 = rv.y * 255.0f; d1 = dv.y * 255.0f; }
        }
        s_rd[y * P_RD + x]     = pack2(r0, d0);
        s_rd[y * P_RD + x + 1] = pack2(r1, d1);
    }
    __syncthreads();

    // ---- Phase 2: horizontal 11-tap, strips of 4; 8 strips x 50 rows ----
    // Task decode puts 16 consecutive y in each half-warp (1 strip) ->
    // conflict-free LDS.64/STS.64 with odd pitches, zero inner-loop ALU.
    for (int task = tid; task < 512; task += 256) {
        int y = (task & 15) | ((task >> 7) << 4);
        if (y < IN_H) {
            int x0 = ((task >> 4) & 7) << 2;
            const u64* base = &s_rd[y * P_RD + x0];
            u64 am[4] = {0, 0, 0, 0};
            u64 aq[4] = {0, 0, 0, 0};
            #pragma unroll
            for (int i = 0; i < 14; i++) {
                u64 v  = base[i];
                u64 sq = mul2(v, v);
                float r, d, rr, dd;
                unpack2(v, r, d);
                unpack2(sq, rr, dd);
                u64 q = pack2(rr + dd, r * d);
                #pragma unroll
                for (int k = 0; k < 4; k++) {
                    int j = i - k;
                    if (j >= 0 && j < 11) {
                        am[k] = fma2(g2[j], v, am[k]);
                        aq[k] = fma2(g2[j], q, aq[k]);
                    }
                }
            }
            int hb = y * P_H + x0;
            #pragma unroll
            for (int k = 0; k < 4; k++) {
                s_hm[hb + k] = am[k];
                s_hq[hb + k] = aq[k];
            }
        }
    }
    __syncthreads();

    // ---- Phase 3: vertical 11-tap, strips of 5 + SSIM + reduce (256 tasks) ----
    float local = 0.0f;
    {
        int x  = tid & 31;
        int y0 = (tid >> 5) * 5;
        u64 am[5] = {0, 0, 0, 0, 0};
        u64 aq[5] = {0, 0, 0, 0, 0};
        const u64* bm = &s_hm[y0 * P_H + x];
        const u64* bq = &s_hq[y0 * P_H + x];
        #pragma unroll
        for (int j = 0; j < 15; j++) {
            u64 hm = bm[j * P_H];
            u64 hq = bq[j * P_H];
            #pragma unroll
            for (int k = 0; k < 5; k++) {
                int t = j - k;
                if (t >= 0 && t < 11) {
                    am[k] = fma2(g2[t], hm, am[k]);
                    aq[k] = fma2(g2[t], hq, aq[k]);
                }
            }
        }
        const float C1 = 6.5025f;
        const float C2 = 58.5225f;
        int ox  = blockIdx.x * TILE_W + x;
        int oyb = blockIdx.y * TILE_H + y0;
        #pragma unroll
        for (int k = 0; k < 5; k++) {
            if (ox < OUT_DIM && (oyb + k) < OUT_DIM) {
                float a, b, srrdd, srd;
                unpack2(am[k], a, b);
                unpack2(aq[k], srrdd, srd);
                float ab  = a * b;
                float cov = srd - ab;
                float var = srrdd - a * a - b * b;
                float num = (2.0f * ab + C1) * (2.0f * cov + C2);
                float den = (a * a + b * b + C1) * (var + C2);
                local += __fdividef(num, den);
            }
        }
    }

    #pragma unroll
    for (int o = 16; o > 0; o >>= 1)
        local += __shfl_down_sync(0xffffffff, local, o);
    if ((tid & 31) == 0) s_red[tid >> 5] = local;
    __syncthreads();
    if (tid < 8) {
        local = s_red[tid];
        #pragma unroll
        for (int o = 4; o > 0; o >>= 1)
            local += __shfl_down_sync(0xff, local, o);
        if (tid == 0)
            atomicAdd(&out[z / 3], local * (1.0f / 732108.0f)); // 1/(3*494^2)
    }
}

extern "C" void kernel_launch(void* const* d_in, const int* in_sizes, int n_in,
                              void* d_out, int out_size) {
    const float* raw = (const float*)d_in[0];
    const float* dst = (const float*)d_in[1];
    float* out = (float*)d_out;

    ssim_zero<<<1, 32>>>(out);
    dim3 grid(16, 13, 96);   // 32x40 tiles over 494x494, z = b*3+c
    ssim_main<<<grid, 256>>>(raw, dst, out);
}